// round 3
// baseline (speedup 1.0000x reference)
#include <cuda_runtime.h>

// DynamicUpsamplingFilter: out[b,c,h,w] = sum_{dy,dx} x_pad[b,c,h+dy,w+dx] * filters[b,dy*3+dx,h,w]
// x: [4,128,180,320] f32, filters: [4,9,180,320] f32, out: [4,128,180,320] f32.
//
// R3: thread owns 4 consecutive w pixels (float4) and 32 channels.
// Halo columns (w-1, w+4) come from warp shuffles of the neighbor lane's
// float4 instead of scalar LDGs (which cost 4 L1 wavefronts each).
// Only lane 0 / lane 31 do a real 1-lane load. Warp wrap / row wrap points
// coincide with image edges where the filter component is zeroed, so
// garbage shuffle data multiplies by zero. L1 wavefronts per channel:
// 40 -> ~18.

constexpr int B = 4, C = 128, H = 180, W = 320;
constexpr int HW = H * W;
constexpr int WQ = W / 4;            // 80 pixel-quads per row
constexpr int CCH = 32;              // channels per thread
constexpr int NCQ = C / CCH;         // 4 channel-quads
constexpr int THREADS = 256;
constexpr int NTHREADS_TOTAL = B * NCQ * H * WQ;   // 230400
constexpr int GRID = NTHREADS_TOTAL / THREADS;     // 900

__global__ __launch_bounds__(THREADS, 3)
void duf_kernel(const float* __restrict__ x,
                const float* __restrict__ f,
                float* __restrict__ out)
{
    int idx  = blockIdx.x * THREADS + threadIdx.x;
    int lane = threadIdx.x & 31;

    // consecutive threads -> consecutive wq for coalescing
    int wq = idx % WQ;
    int t  = idx / WQ;
    int h  = t % H;
    t /= H;
    int cq = t % NCQ;
    int b  = t / NCQ;
    int w  = wq * 4;

    // ---- load 9 filter tap vectors (pixels w..w+3) into registers ----
    const float* fp = f + (size_t)b * 9 * HW + (size_t)h * W + w;
    float4 fv[9];
#pragma unroll
    for (int i = 0; i < 9; ++i)
        fv[i] = *(const float4*)(fp + (size_t)i * HW);

    // vertical boundary: zero whole tap rows
    if (h == 0) {
#pragma unroll
        for (int i = 0; i < 3; ++i) fv[i] = make_float4(0.f, 0.f, 0.f, 0.f);
    }
    if (h == H - 1) {
#pragma unroll
        for (int i = 6; i < 9; ++i) fv[i] = make_float4(0.f, 0.f, 0.f, 0.f);
    }
    // horizontal boundary: pixel 0 loses dx=-1 taps, pixel 3 loses dx=+1 taps
    if (w == 0)     { fv[0].x = 0.f; fv[3].x = 0.f; fv[6].x = 0.f; }
    if (w == W - 4) { fv[2].w = 0.f; fv[5].w = 0.f; fv[8].w = 0.f; }

    // clamped row offsets (dead loads land in-bounds; their filter row is zero)
    int roff[3];
    roff[0] = (h > 0)     ? -W : 0;
    roff[1] = 0;
    roff[2] = (h < H - 1) ?  W : 0;
    // clamped scalar offsets for the edge lanes only
    int offm1 = (w > 0)     ? -1 : 0;   // column w-1
    int offp4 = (w + 4 < W) ?  4 : 3;   // column w+4
    bool ln0  = (lane == 0);
    bool ln31 = (lane == 31);

    const float* xp = x   + ((size_t)b * C + cq * CCH) * HW + (size_t)h * W + w;
    float*       op = out + ((size_t)b * C + cq * CCH) * HW + (size_t)h * W + w;

#pragma unroll 2
    for (int c = 0; c < CCH; ++c) {
        const float* xc = xp + (size_t)c * HW;
        float a0 = 0.f, a1 = 0.f, a2 = 0.f, a3 = 0.f;
#pragma unroll
        for (int r = 0; r < 3; ++r) {
            const float* row = xc + roff[r];
            float4 m = *(const float4*)row;   // columns w..w+3
            // halo columns from neighbor lanes (garbage at edges is
            // multiplied by a zeroed filter component)
            float vm1 = __shfl_up_sync(0xffffffffu,  m.w, 1);
            float vp4 = __shfl_down_sync(0xffffffffu, m.x, 1);
            if (ln0)  vm1 = __ldg(row + offm1);
            if (ln31) vp4 = __ldg(row + offp4);
            float4 F0 = fv[3 * r + 0];        // dx=-1 taps, pixels 0..3
            float4 F1 = fv[3 * r + 1];        // dx= 0
            float4 F2 = fv[3 * r + 2];        // dx=+1
            a0 = fmaf(vm1, F0.x, a0); a0 = fmaf(m.x, F1.x, a0); a0 = fmaf(m.y, F2.x, a0);
            a1 = fmaf(m.x, F0.y, a1); a1 = fmaf(m.y, F1.y, a1); a1 = fmaf(m.z, F2.y, a1);
            a2 = fmaf(m.y, F0.z, a2); a2 = fmaf(m.z, F1.z, a2); a2 = fmaf(m.w, F2.z, a2);
            a3 = fmaf(m.z, F0.w, a3); a3 = fmaf(m.w, F1.w, a3); a3 = fmaf(vp4, F2.w, a3);
        }
        *(float4*)(op + (size_t)c * HW) = make_float4(a0, a1, a2, a3);
    }
}

extern "C" void kernel_launch(void* const* d_in, const int* in_sizes, int n_in,
                              void* d_out, int out_size)
{
    const float* x = (const float*)d_in[0];   // [4,128,180,320]
    const float* f = (const float*)d_in[1];   // [4,9,180,320]
    float* out = (float*)d_out;               // [4,128,180,320]

    duf_kernel<<<GRID, THREADS>>>(x, f, out);
}

// round 4
// speedup vs baseline: 1.4975x; 1.4975x over previous
#include <cuda_runtime.h>

// DynamicUpsamplingFilter: out[b,c,h,w] = sum_{dy,dx} x_pad[b,c,h+dy,w+dx] * filters[b,dy*3+dx,h,w]
// x: [4,128,180,320] f32, filters: [4,9,180,320] f32, out: [4,128,180,320] f32.
//
// R4 = R2 (best: 64us) + occupancy fix. R2 was latency-limited (occ 24.3%,
// L1 57.8% not saturated). __launch_bounds__(256,3) caps regs at ~85 ->
// 3 blocks/SM -> 50% more warps in flight. Halo loads issue before the
// vector load in each row group for maximal load batching.

constexpr int B = 4, C = 128, H = 180, W = 320;
constexpr int HW = H * W;
constexpr int WQ = W / 4;            // 80 pixel-quads per row
constexpr int CCH = 32;              // channels per thread
constexpr int NCQ = C / CCH;         // 4 channel-quads
constexpr int THREADS = 256;
constexpr int NTHREADS_TOTAL = B * NCQ * H * WQ;   // 230400
constexpr int GRID = NTHREADS_TOTAL / THREADS;     // 900

__global__ __launch_bounds__(THREADS, 3)
void duf_kernel(const float* __restrict__ x,
                const float* __restrict__ f,
                float* __restrict__ out)
{
    int idx = blockIdx.x * THREADS + threadIdx.x;

    // consecutive threads -> consecutive wq for coalescing
    int wq = idx % WQ;
    int t  = idx / WQ;
    int h  = t % H;
    t /= H;
    int cq = t % NCQ;
    int b  = t / NCQ;
    int w  = wq * 4;

    // ---- load 9 filter tap vectors (pixels w..w+3) into registers ----
    const float* fp = f + (size_t)b * 9 * HW + (size_t)h * W + w;
    float4 fv[9];
#pragma unroll
    for (int i = 0; i < 9; ++i)
        fv[i] = *(const float4*)(fp + (size_t)i * HW);

    // vertical boundary: zero whole tap rows
    if (h == 0) {
#pragma unroll
        for (int i = 0; i < 3; ++i) fv[i] = make_float4(0.f, 0.f, 0.f, 0.f);
    }
    if (h == H - 1) {
#pragma unroll
        for (int i = 6; i < 9; ++i) fv[i] = make_float4(0.f, 0.f, 0.f, 0.f);
    }
    // horizontal boundary: pixel 0 loses dx=-1 taps, pixel 3 loses dx=+1 taps
    if (w == 0)     { fv[0].x = 0.f; fv[3].x = 0.f; fv[6].x = 0.f; }
    if (w == W - 4) { fv[2].w = 0.f; fv[5].w = 0.f; fv[8].w = 0.f; }

    // clamped offsets (dead loads land in-bounds; their filter is zero)
    int roff[3];
    roff[0] = (h > 0)     ? -W : 0;
    roff[1] = 0;
    roff[2] = (h < H - 1) ?  W : 0;
    int offm1 = (w > 0)     ? -1 : 0;   // column w-1
    int offp4 = (w + 4 < W) ?  4 : 3;   // column w+4

    const float* xp = x   + ((size_t)b * C + cq * CCH) * HW + (size_t)h * W + w;
    float*       op = out + ((size_t)b * C + cq * CCH) * HW + (size_t)h * W + w;

#pragma unroll 2
    for (int c = 0; c < CCH; ++c) {
        const float* xc = xp + (size_t)c * HW;

        // issue all 9 loads for this channel up front (independent)
        float  vm1[3], vp4[3];
        float4 m[3];
#pragma unroll
        for (int r = 0; r < 3; ++r) {
            const float* row = xc + roff[r];
            vm1[r] = __ldg(row + offm1);      // column w-1
            vp4[r] = __ldg(row + offp4);      // column w+4
            m[r]   = *(const float4*)row;     // columns w..w+3
        }

        float a0 = 0.f, a1 = 0.f, a2 = 0.f, a3 = 0.f;
#pragma unroll
        for (int r = 0; r < 3; ++r) {
            float4 F0 = fv[3 * r + 0];        // dx=-1 taps, pixels 0..3
            float4 F1 = fv[3 * r + 1];        // dx= 0
            float4 F2 = fv[3 * r + 2];        // dx=+1
            a0 = fmaf(vm1[r], F0.x, a0); a0 = fmaf(m[r].x, F1.x, a0); a0 = fmaf(m[r].y, F2.x, a0);
            a1 = fmaf(m[r].x, F0.y, a1); a1 = fmaf(m[r].y, F1.y, a1); a1 = fmaf(m[r].z, F2.y, a1);
            a2 = fmaf(m[r].y, F0.z, a2); a2 = fmaf(m[r].z, F1.z, a2); a2 = fmaf(m[r].w, F2.z, a2);
            a3 = fmaf(m[r].z, F0.w, a3); a3 = fmaf(m[r].w, F1.w, a3); a3 = fmaf(vp4[r], F2.w, a3);
        }
        *(float4*)(op + (size_t)c * HW) = make_float4(a0, a1, a2, a3);
    }
}

extern "C" void kernel_launch(void* const* d_in, const int* in_sizes, int n_in,
                              void* d_out, int out_size)
{
    const float* x = (const float*)d_in[0];   // [4,128,180,320]
    const float* f = (const float*)d_in[1];   // [4,9,180,320]
    float* out = (float*)d_out;               // [4,128,180,320]

    duf_kernel<<<GRID, THREADS>>>(x, f, out);
}